// round 5
// baseline (speedup 1.0000x reference)
#include <cuda_runtime.h>
#include <cstdint>

#define Bb 8
#define Hh 8
#define Nq 1024
#define Cc 256
#define HD 64
#define BH (Bb*Hh)

// ---------------- scratch (device globals; no allocation allowed) ----------
__device__ float g_Qb[BH*Nq*HD];   // [b][h][n][d]  16MB
__device__ float g_Kb[BH*Nq*HD];   // [b][h][n][d]  16MB (holds 1/16 scale after norm)
__device__ float g_red_s[128];
__device__ float g_red_q[128];
__device__ float g_bnp[2][Hh][2];  // [tensor][head][{scale,shift}]

// ---------------- f32x2 helpers --------------------------------------------
__device__ __forceinline__ unsigned long long splat_f32(float x){
    unsigned long long r;
    asm("mov.b64 %0, {%1, %1};" : "=l"(r) : "f"(x));
    return r;
}
__device__ __forceinline__ void ffma2(unsigned long long &d,
                                      unsigned long long a,
                                      unsigned long long b){
    asm("fma.rn.f32x2 %0, %1, %2, %0;" : "+l"(d) : "l"(a), "l"(b));
}
__device__ __forceinline__ float2 unpack2(unsigned long long v){
    float2 r;
    asm("mov.b64 {%0, %1}, %2;" : "=f"(r.x), "=f"(r.y) : "l"(v));
    return r;
}

// ---------------- 1) projection GEMM  q,k = x @ W^T ------------------------
__global__ __launch_bounds__(256) void proj_kernel(const float* __restrict__ x,
                                                   const float* __restrict__ qw,
                                                   const float* __restrict__ kw){
    __shared__ float Ast[16][68];
    __shared__ float Bst[16][68];
    const int tid = threadIdx.x;
    const int tx = tid & 15, ty = tid >> 4;
    const int bm = blockIdx.y * 64;
    const int cb = blockIdx.x;            // 0..15 (64-col slab == one head chunk)
    const float* Wp = (cb < 8) ? (qw + (size_t)cb*64*Cc) : (kw + (size_t)(cb-8)*64*Cc);
    float* outbuf = (cb < 8) ? g_Qb : g_Kb;
    const int hsel = cb & 7;

    unsigned long long acc[4][2];
    #pragma unroll
    for (int i=0;i<4;i++){ acc[i][0]=0ull; acc[i][1]=0ull; }

    const int row_ld = tid >> 2;          // 0..63
    const int kq = tid & 3;               // 0..3

    for (int kc = 0; kc < 16; kc++){
        const int k0 = kc*16;
        float4 a4 = *reinterpret_cast<const float4*>(x  + (size_t)(bm + row_ld)*Cc + k0 + kq*4);
        float4 b4 = *reinterpret_cast<const float4*>(Wp + (size_t)row_ld*Cc        + k0 + kq*4);
        Ast[kq*4+0][row_ld]=a4.x; Ast[kq*4+1][row_ld]=a4.y;
        Ast[kq*4+2][row_ld]=a4.z; Ast[kq*4+3][row_ld]=a4.w;
        Bst[kq*4+0][row_ld]=b4.x; Bst[kq*4+1][row_ld]=b4.y;
        Bst[kq*4+2][row_ld]=b4.z; Bst[kq*4+3][row_ld]=b4.w;
        __syncthreads();
        #pragma unroll
        for (int k=0;k<16;k++){
            float4 av = *reinterpret_cast<const float4*>(&Ast[k][ty*4]);
            const unsigned long long* bpp =
                reinterpret_cast<const unsigned long long*>(&Bst[k][tx*4]);
            unsigned long long bp0 = bpp[0], bp1 = bpp[1];
            float avv[4] = {av.x, av.y, av.z, av.w};
            #pragma unroll
            for (int i=0;i<4;i++){
                unsigned long long ap = splat_f32(avv[i]);
                ffma2(acc[i][0], ap, bp0);
                ffma2(acc[i][1], ap, bp1);
            }
        }
        __syncthreads();
    }
    #pragma unroll
    for (int i=0;i<4;i++){
        const int m = bm + ty*4 + i;
        const int b = m >> 10, n = m & 1023;
        float2 p0 = unpack2(acc[i][0]);
        float2 p1 = unpack2(acc[i][1]);
        float4 o = make_float4(p0.x, p0.y, p1.x, p1.y);
        float* dst = outbuf + (((size_t)(b*Hh + hsel))*Nq + n)*HD + tx*4;
        *reinterpret_cast<float4*>(dst) = o;
    }
}

// ---------------- 2) BN stats ----------------------------------------------
__global__ __launch_bounds__(256) void stats_kernel(){
    __shared__ float ss[256], sq[256];
    const int t = blockIdx.x >> 6;
    const int idx = blockIdx.x & 63;
    const float* base = (t ? g_Kb : g_Qb) + (size_t)idx * 65536;
    const float4* b4p = reinterpret_cast<const float4*>(base);
    float s = 0.f, q = 0.f;
    for (int i = threadIdx.x; i < 16384; i += 256){
        float4 v = b4p[i];
        s += (v.x + v.y) + (v.z + v.w);
        q += v.x*v.x + v.y*v.y + v.z*v.z + v.w*v.w;
    }
    ss[threadIdx.x] = s; sq[threadIdx.x] = q;
    __syncthreads();
    for (int o = 128; o > 0; o >>= 1){
        if (threadIdx.x < o){
            ss[threadIdx.x] += ss[threadIdx.x+o];
            sq[threadIdx.x] += sq[threadIdx.x+o];
        }
        __syncthreads();
    }
    if (threadIdx.x == 0){ g_red_s[blockIdx.x] = ss[0]; g_red_q[blockIdx.x] = sq[0]; }
}

__global__ void bn_finalize_kernel(const float* __restrict__ bnw,
                                   const float* __restrict__ bnb){
    const int tid = threadIdx.x;
    if (tid < 16){
        const int t = tid >> 3, h = tid & 7;
        float S = 0.f, Q = 0.f;
        for (int b = 0; b < 8; b++){
            const int j = t*64 + b*8 + h;
            S += g_red_s[j]; Q += g_red_q[j];
        }
        const float inv = 1.0f / 524288.0f;
        const float mean = S * inv;
        const float var  = Q * inv - mean*mean;
        const float sc = bnw[h] * rsqrtf(var + 1e-5f);
        const float sh = bnb[h] - mean * sc;
        g_bnp[t][h][0] = sc; g_bnp[t][h][1] = sh;
    }
}

// ---------------- 3) BN affine + L2 normalize (in place) -------------------
// K additionally scaled by 1/16 (= 1/sqrt(256) score scale).
__global__ __launch_bounds__(256) void norm_kernel(){
    const int tid = threadIdx.x;
    const int w = tid >> 5, l = tid & 31;
    const int row = blockIdx.x*8 + w;             // 0..131071
    const int t  = row >> 16;
    const int r2 = row & 65535;                   // (b*8+h)*1024 + n
    const int h  = (r2 >> 10) & 7;
    float* base = (t ? g_Kb : g_Qb) + (size_t)r2 * 64;
    float2 v = reinterpret_cast<float2*>(base)[l];
    const float sc = g_bnp[t][h][0], sf = g_bnp[t][h][1];
    v.x = fmaf(v.x, sc, sf);
    v.y = fmaf(v.y, sc, sf);
    float ssum = v.x*v.x + v.y*v.y;
    #pragma unroll
    for (int o = 16; o > 0; o >>= 1) ssum += __shfl_xor_sync(0xffffffffu, ssum, o);
    float nrm = fmaxf(sqrtf(ssum), 1e-12f);
    const float r = (t ? 0.0625f : 1.0f) / nrm;
    v.x *= r; v.y *= r;
    reinterpret_cast<float2*>(base)[l] = v;
}

// ---------------- 4) fused scores GEMM + sparsemax(axis=n) + store ---------
// CTA = (m-tile 32, bh). Thread tile 8m x 8n (32 f32x2 accs, n-pair packed).
// tm = tid&3 selects 8-m group, tn = tid>>2 selects 8-n group.
// Q staged as bank-swizzled scalar rows (word = n + 2*(n>>3)); K staged as
// duplicated float2 so fma2 operands come straight from LDS.64 (no splats).
// Epilogue: conflict-free smem transpose -> R1's proven sparsemax layout.
#define QROW 1280                          /* floats per swizzled 1024-n row */
#define QBUF (8*QROW)                      /* floats per d-chunk buffer      */
#define SOFF_QST  0                        /* 2 x 40960B = 81920             */
#define SOFF_KD   81920                    /* float2[64][32] = 16384         */
#define SOFF_STG  0                        /* overlay (post-mainloop): [1024][33] f = 135168 */
#define SOFF_REDS 135168
#define SOFF_REDC 137216
#define SOFF_TAUS 139264
#define SOFF_FLAG 139392
#define ATTN_SMEM 139520

__global__ __launch_bounds__(512, 1) void attn_kernel(float* __restrict__ out){
    extern __shared__ char smem[];
    float*  qst = reinterpret_cast<float*>(smem + SOFF_QST);
    float2* kd  = reinterpret_cast<float2*>(smem + SOFF_KD);
    float*  stg = reinterpret_cast<float*>(smem + SOFF_STG);
    float*  red_s = reinterpret_cast<float*>(smem + SOFF_REDS);
    float*  red_c = reinterpret_cast<float*>(smem + SOFF_REDC);
    float*  taus  = reinterpret_cast<float*>(smem + SOFF_TAUS);
    int*    flagp = reinterpret_cast<int*>(smem + SOFF_FLAG);

    const int tid = threadIdx.x;
    const int w = tid >> 5, l = tid & 31;
    const int tm = tid & 3, tn = tid >> 2;     // 4 m-groups x 128 n-groups
    const int bh = blockIdx.y;
    const int m0 = blockIdx.x * 32;

    const float* Qg = g_Qb + (size_t)bh * Nq * 64;
    const float* Kg = g_Kb + (size_t)bh * Nq * 64;

    // ---- K staging: duplicate each K[m][d] into float2{v,v}, layout kd[d][m]
    {
        const int m = tid & 31, dq = tid >> 5;     // dq 0..15
        float4 kv = *reinterpret_cast<const float4*>(Kg + (size_t)(m0 + m)*64 + dq*4);
        kd[(dq*4+0)*32 + m] = make_float2(kv.x, kv.x);
        kd[(dq*4+1)*32 + m] = make_float2(kv.y, kv.y);
        kd[(dq*4+2)*32 + m] = make_float2(kv.z, kv.z);
        kd[(dq*4+3)*32 + m] = make_float2(kv.w, kv.w);
    }
    // ---- Q chunk 0 -> buffer 0 (swizzled scalar rows)
    const int n0 = tid, n1 = tid + 512;
    const int w0 = n0 + 2*(n0 >> 3);
    const int w1 = n1 + 2*(n1 >> 3);
    {
        float4 a0 = *reinterpret_cast<const float4*>(Qg + (size_t)n0*64);
        float4 a1 = *reinterpret_cast<const float4*>(Qg + (size_t)n0*64 + 4);
        float4 a2 = *reinterpret_cast<const float4*>(Qg + (size_t)n1*64);
        float4 a3 = *reinterpret_cast<const float4*>(Qg + (size_t)n1*64 + 4);
        qst[0*QROW+w0]=a0.x; qst[1*QROW+w0]=a0.y; qst[2*QROW+w0]=a0.z; qst[3*QROW+w0]=a0.w;
        qst[4*QROW+w0]=a1.x; qst[5*QROW+w0]=a1.y; qst[6*QROW+w0]=a1.z; qst[7*QROW+w0]=a1.w;
        qst[0*QROW+w1]=a2.x; qst[1*QROW+w1]=a2.y; qst[2*QROW+w1]=a2.z; qst[3*QROW+w1]=a2.w;
        qst[4*QROW+w1]=a3.x; qst[5*QROW+w1]=a3.y; qst[6*QROW+w1]=a3.z; qst[7*QROW+w1]=a3.w;
    }
    __syncthreads();

    unsigned long long acc[8][4];
    #pragma unroll
    for (int mi = 0; mi < 8; mi++)
        #pragma unroll
        for (int nj = 0; nj < 4; nj++) acc[mi][nj] = 0ull;

    const int qb = 10*tn;    // swizzled base word for this thread's 8-n group

    for (int c = 0; c < 8; c++){
        const int buf = c & 1;
        float4 p0, p1, p2, p3;
        if (c < 7){
            const int d0 = (c+1)*8;
            p0 = *reinterpret_cast<const float4*>(Qg + (size_t)n0*64 + d0);
            p1 = *reinterpret_cast<const float4*>(Qg + (size_t)n0*64 + d0 + 4);
            p2 = *reinterpret_cast<const float4*>(Qg + (size_t)n1*64 + d0);
            p3 = *reinterpret_cast<const float4*>(Qg + (size_t)n1*64 + d0 + 4);
        }
        const float* qbase = qst + buf*QBUF;
        #pragma unroll
        for (int dd = 0; dd < 8; dd++){
            const int d = c*8 + dd;
            const unsigned long long* krow =
                reinterpret_cast<const unsigned long long*>(kd + d*32 + tm*8);
            const float* qrow = qbase + dd*QROW + qb;
            unsigned long long qpv[4];
            #pragma unroll
            for (int nj = 0; nj < 4; nj++)
                qpv[nj] = *reinterpret_cast<const unsigned long long*>(qrow + 2*nj);
            #pragma unroll
            for (int mi = 0; mi < 8; mi++){
                unsigned long long kp = krow[mi];
                #pragma unroll
                for (int nj = 0; nj < 4; nj++)
                    ffma2(acc[mi][nj], kp, qpv[nj]);
            }
        }
        if (c < 7){
            float* dstb = qst + (buf^1)*QBUF;
            dstb[0*QROW+w0]=p0.x; dstb[1*QROW+w0]=p0.y; dstb[2*QROW+w0]=p0.z; dstb[3*QROW+w0]=p0.w;
            dstb[4*QROW+w0]=p1.x; dstb[5*QROW+w0]=p1.y; dstb[6*QROW+w0]=p1.z; dstb[7*QROW+w0]=p1.w;
            dstb[0*QROW+w1]=p2.x; dstb[1*QROW+w1]=p2.y; dstb[2*QROW+w1]=p2.z; dstb[3*QROW+w1]=p2.w;
            dstb[4*QROW+w1]=p3.x; dstb[5*QROW+w1]=p3.y; dstb[6*QROW+w1]=p3.z; dstb[7*QROW+w1]=p3.w;
        }
        __syncthreads();
    }

    // ---- transpose scores into staging (overlays dead Q/K smem) -----------
    // staging[r][m], r = (n&7)*128 + (n>>3); write pattern conflict-free.
    #pragma unroll
    for (int mi = 0; mi < 8; mi++){
        #pragma unroll
        for (int nj = 0; nj < 4; nj++){
            float2 p = unpack2(acc[mi][nj]);
            const int r0 = (2*nj+0)*128 + tn;
            const int r1 = (2*nj+1)*128 + tn;
            stg[r0*33 + tm*8 + mi] = p.x;
            stg[r1*33 + tm*8 + mi] = p.y;
        }
    }
    __syncthreads();

    // ---- read own column: col = l, n-slab = w (64 rows) -------------------
    float z[64];
    #pragma unroll
    for (int i = 0; i < 64; i++) z[i] = stg[(w*64 + i)*33 + l];

    // ---- Michelot fixed point for sparsemax tau over the 1024-row column --
    float tau = -1.0f;
    for (int iter = 0; iter < 48; iter++){
        float s = 0.f, ccount = 0.f;
        #pragma unroll
        for (int i = 0; i < 64; i++){
            if (z[i] > tau){ s += z[i]; ccount += 1.0f; }
        }
        red_s[w*32 + l] = s; red_c[w*32 + l] = ccount;
        __syncthreads();
        if (w == 0){
            float S = 0.f, Cn = 0.f;
            #pragma unroll
            for (int ww = 0; ww < 16; ww++){ S += red_s[ww*32 + l]; Cn += red_c[ww*32 + l]; }
            float nt = (Cn > 0.f) ? (S - 1.0f)/Cn : tau;
            unsigned bal = __ballot_sync(0xffffffffu, nt != tau);
            taus[l] = nt;
            if (l == 0) *flagp = (bal != 0u);
        }
        __syncthreads();
        tau = taus[l];
        if (!(*flagp)) break;
    }

    // ---- store: out[b][n][h*1024 + m0 + l], n recovered from r ------------
    const int b = bh >> 3, h = bh & 7;
    const size_t obase = (size_t)b*8388608 + (size_t)h*1024 + m0 + l;
    #pragma unroll
    for (int i = 0; i < 64; i++){
        const int r = w*64 + i;
        const int n = ((r & 127) << 3) + (r >> 7);
        float v = z[i] - tau;
        out[obase + (size_t)n*8192] = v > 0.f ? v : 0.f;
    }
}

// ---------------- launcher --------------------------------------------------
extern "C" void kernel_launch(void* const* d_in, const int* in_sizes, int n_in,
                              void* d_out, int out_size){
    const float* x   = (const float*)d_in[0];
    const float* qw  = (const float*)d_in[1];
    const float* kw  = (const float*)d_in[2];
    const float* bnw = (const float*)d_in[3];
    const float* bnb = (const float*)d_in[4];
    float* out = (float*)d_out;
    (void)in_sizes; (void)n_in; (void)out_size;

    cudaFuncSetAttribute(attn_kernel,
                         cudaFuncAttributeMaxDynamicSharedMemorySize, ATTN_SMEM);

    proj_kernel<<<dim3(16, 128), 256>>>(x, qw, kw);
    stats_kernel<<<128, 256>>>();
    bn_finalize_kernel<<<1, 32>>>(bnw, bnb);
    norm_kernel<<<16384, 256>>>();
    attn_kernel<<<dim3(32, 64), 512, ATTN_SMEM>>>(out);
}

// round 7
// speedup vs baseline: 1.1748x; 1.1748x over previous
#include <cuda_runtime.h>
#include <cstdint>

#define Bb 8
#define Hh 8
#define Nq 1024
#define Cc 256
#define HD 64
#define BH (Bb*Hh)

// ---------------- scratch (device globals; no allocation allowed) ----------
__device__ float g_Qb[BH*Nq*HD];   // [b][h][n][d]  16MB
__device__ float g_Kb[BH*Nq*HD];   // [b][h][n][d]  16MB (holds 1/16 scale after norm)
__device__ float g_red_s[128];
__device__ float g_red_q[128];

// ---------------- f32x2 helpers --------------------------------------------
__device__ __forceinline__ unsigned long long splat_f32(float x){
    unsigned long long r;
    asm("mov.b64 %0, {%1, %1};" : "=l"(r) : "f"(x));
    return r;
}
__device__ __forceinline__ void ffma2(unsigned long long &d,
                                      unsigned long long a,
                                      unsigned long long b){
    asm("fma.rn.f32x2 %0, %1, %2, %0;" : "+l"(d) : "l"(a), "l"(b));
}
__device__ __forceinline__ float2 unpack2(unsigned long long v){
    float2 r;
    asm("mov.b64 {%0, %1}, %2;" : "=f"(r.x), "=f"(r.y) : "l"(v));
    return r;
}

// ---------------- 1) projection GEMM  q,k = x @ W^T ------------------------
__global__ __launch_bounds__(256) void proj_kernel(const float* __restrict__ x,
                                                   const float* __restrict__ qw,
                                                   const float* __restrict__ kw){
    __shared__ float Ast[16][68];
    __shared__ float Bst[16][68];
    const int tid = threadIdx.x;
    const int tx = tid & 15, ty = tid >> 4;
    const int bm = blockIdx.y * 64;
    const int cb = blockIdx.x;            // 0..15 (64-col slab == one head chunk)
    const float* Wp = (cb < 8) ? (qw + (size_t)cb*64*Cc) : (kw + (size_t)(cb-8)*64*Cc);
    float* outbuf = (cb < 8) ? g_Qb : g_Kb;
    const int hsel = cb & 7;

    unsigned long long acc[4][2];
    #pragma unroll
    for (int i=0;i<4;i++){ acc[i][0]=0ull; acc[i][1]=0ull; }

    const int row_ld = tid >> 2;          // 0..63
    const int kq = tid & 3;               // 0..3

    for (int kc = 0; kc < 16; kc++){
        const int k0 = kc*16;
        float4 a4 = *reinterpret_cast<const float4*>(x  + (size_t)(bm + row_ld)*Cc + k0 + kq*4);
        float4 b4 = *reinterpret_cast<const float4*>(Wp + (size_t)row_ld*Cc        + k0 + kq*4);
        Ast[kq*4+0][row_ld]=a4.x; Ast[kq*4+1][row_ld]=a4.y;
        Ast[kq*4+2][row_ld]=a4.z; Ast[kq*4+3][row_ld]=a4.w;
        Bst[kq*4+0][row_ld]=b4.x; Bst[kq*4+1][row_ld]=b4.y;
        Bst[kq*4+2][row_ld]=b4.z; Bst[kq*4+3][row_ld]=b4.w;
        __syncthreads();
        #pragma unroll
        for (int k=0;k<16;k++){
            float4 av = *reinterpret_cast<const float4*>(&Ast[k][ty*4]);
            const unsigned long long* bpp =
                reinterpret_cast<const unsigned long long*>(&Bst[k][tx*4]);
            unsigned long long bp0 = bpp[0], bp1 = bpp[1];
            float avv[4] = {av.x, av.y, av.z, av.w};
            #pragma unroll
            for (int i=0;i<4;i++){
                unsigned long long ap = splat_f32(avv[i]);
                ffma2(acc[i][0], ap, bp0);
                ffma2(acc[i][1], ap, bp1);
            }
        }
        __syncthreads();
    }
    #pragma unroll
    for (int i=0;i<4;i++){
        const int m = bm + ty*4 + i;
        const int b = m >> 10, n = m & 1023;
        float2 p0 = unpack2(acc[i][0]);
        float2 p1 = unpack2(acc[i][1]);
        float4 o = make_float4(p0.x, p0.y, p1.x, p1.y);
        float* dst = outbuf + (((size_t)(b*Hh + hsel))*Nq + n)*HD + tx*4;
        *reinterpret_cast<float4*>(dst) = o;
    }
}

// ---------------- 2) BN stats ----------------------------------------------
__global__ __launch_bounds__(256) void stats_kernel(){
    __shared__ float ss[256], sq[256];
    const int t = blockIdx.x >> 6;
    const int idx = blockIdx.x & 63;
    const float* base = (t ? g_Kb : g_Qb) + (size_t)idx * 65536;
    const float4* b4p = reinterpret_cast<const float4*>(base);
    float s = 0.f, q = 0.f;
    for (int i = threadIdx.x; i < 16384; i += 256){
        float4 v = b4p[i];
        s += (v.x + v.y) + (v.z + v.w);
        q += v.x*v.x + v.y*v.y + v.z*v.z + v.w*v.w;
    }
    ss[threadIdx.x] = s; sq[threadIdx.x] = q;
    __syncthreads();
    for (int o = 128; o > 0; o >>= 1){
        if (threadIdx.x < o){
            ss[threadIdx.x] += ss[threadIdx.x+o];
            sq[threadIdx.x] += sq[threadIdx.x+o];
        }
        __syncthreads();
    }
    if (threadIdx.x == 0){ g_red_s[blockIdx.x] = ss[0]; g_red_q[blockIdx.x] = sq[0]; }
}

// ---------------- 3) BN finalize (redundant per block) + affine + L2 norm --
// K additionally scaled by 1/16 (= 1/sqrt(256) score scale).
__global__ __launch_bounds__(256) void norm_kernel(const float* __restrict__ bnw,
                                                   const float* __restrict__ bnb){
    __shared__ float s_bnp[2][8][2];
    const int tid = threadIdx.x;
    if (tid < 16){
        const int t = tid >> 3, h = tid & 7;
        float S = 0.f, Q = 0.f;
        #pragma unroll
        for (int b = 0; b < 8; b++){
            const int j = t*64 + b*8 + h;
            S += g_red_s[j]; Q += g_red_q[j];
        }
        const float inv = 1.0f / 524288.0f;
        const float mean = S * inv;
        const float var  = Q * inv - mean*mean;
        const float sc = bnw[h] * rsqrtf(var + 1e-5f);
        const float sh = bnb[h] - mean * sc;
        s_bnp[t][h][0] = sc; s_bnp[t][h][1] = sh;
    }
    __syncthreads();

    const int w = tid >> 5, l = tid & 31;
    const int row = blockIdx.x*8 + w;             // 0..131071
    const int t  = row >> 16;
    const int r2 = row & 65535;                   // (b*8+h)*1024 + n
    const int h  = (r2 >> 10) & 7;
    float* base = (t ? g_Kb : g_Qb) + (size_t)r2 * 64;
    float2 v = reinterpret_cast<float2*>(base)[l];
    const float sc = s_bnp[t][h][0], sf = s_bnp[t][h][1];
    v.x = fmaf(v.x, sc, sf);
    v.y = fmaf(v.y, sc, sf);
    float ssum = v.x*v.x + v.y*v.y;
    #pragma unroll
    for (int o = 16; o > 0; o >>= 1) ssum += __shfl_xor_sync(0xffffffffu, ssum, o);
    float nrm = fmaxf(sqrtf(ssum), 1e-12f);
    const float r = (t ? 0.0625f : 1.0f) / nrm;
    v.x *= r; v.y *= r;
    reinterpret_cast<float2*>(base)[l] = v;
}

// ---------------- 4) fused scores GEMM + sparsemax(axis=n) + store ---------
// CTA = (m-tile 32, bh). Thread tile 8m x 8n, n-pairs packed in f32x2.
// tm = w&3 (warp-uniform m-group -> K LDS are pure broadcasts),
// tn = (w>>2)*32 + l. Q staged with even-stride swizzle word(n) = n + 2*(n>>3)
// (stride 10: 8B-aligned LDS.64, conflict-free per 16-lane phase).
// Epilogue: conflict-free transpose to stg, Michelot sparsemax with
// replicated cross-warp reduction + __syncthreads_count convergence.
#define QROW 1280                          /* floats per swizzled 1024-n row */
#define QBUF (8*QROW)                      /* floats per d-chunk buffer      */
#define SOFF_QST  0                        /* 2 x 40960B = 81920             */
#define SOFF_KD   81920                    /* float2[64][32] = 16384         */
#define SOFF_STG  0                        /* overlay: float[1024][33] = 135168 */
#define SOFF_REDS 135168
#define SOFF_REDC 137216
#define ATTN_SMEM 139264

__global__ __launch_bounds__(512, 1) void attn_kernel(float* __restrict__ out){
    extern __shared__ char smem[];
    float*  qst   = reinterpret_cast<float*>(smem + SOFF_QST);
    float2* kd    = reinterpret_cast<float2*>(smem + SOFF_KD);
    float*  stg   = reinterpret_cast<float*>(smem + SOFF_STG);
    float*  red_s = reinterpret_cast<float*>(smem + SOFF_REDS);
    float*  red_c = reinterpret_cast<float*>(smem + SOFF_REDC);

    const int tid = threadIdx.x;
    const int w = tid >> 5, l = tid & 31;
    const int tm = w & 3;                  // warp-uniform m-group
    const int tn = (w >> 2)*32 + l;        // 0..127 n-group
    const int bh = blockIdx.y;
    const int m0 = blockIdx.x * 32;

    const float* Qg = g_Qb + (size_t)bh * Nq * 64;
    const float* Kg = g_Kb + (size_t)bh * Nq * 64;

    // ---- K staging: kd[d][m] = {K[m][d], K[m][d]} (dup for f32x2) ---------
    {
        const int m = tid & 31, dq = tid >> 5;     // dq 0..15
        float4 kv = *reinterpret_cast<const float4*>(Kg + (size_t)(m0 + m)*64 + dq*4);
        kd[(dq*4+0)*32 + m] = make_float2(kv.x, kv.x);
        kd[(dq*4+1)*32 + m] = make_float2(kv.y, kv.y);
        kd[(dq*4+2)*32 + m] = make_float2(kv.z, kv.z);
        kd[(dq*4+3)*32 + m] = make_float2(kv.w, kv.w);
    }
    // ---- Q chunk 0 -> buffer 0 (even-stride swizzled scalar rows) ---------
    const int n0 = tid, n1 = tid + 512;
    const int w0 = n0 + 2*(n0 >> 3);
    const int w1 = n1 + 2*(n1 >> 3);
    {
        float4 a0 = *reinterpret_cast<const float4*>(Qg + (size_t)n0*64);
        float4 a1 = *reinterpret_cast<const float4*>(Qg + (size_t)n0*64 + 4);
        float4 a2 = *reinterpret_cast<const float4*>(Qg + (size_t)n1*64);
        float4 a3 = *reinterpret_cast<const float4*>(Qg + (size_t)n1*64 + 4);
        qst[0*QROW+w0]=a0.x; qst[1*QROW+w0]=a0.y; qst[2*QROW+w0]=a0.z; qst[3*QROW+w0]=a0.w;
        qst[4*QROW+w0]=a1.x; qst[5*QROW+w0]=a1.y; qst[6*QROW+w0]=a1.z; qst[7*QROW+w0]=a1.w;
        qst[0*QROW+w1]=a2.x; qst[1*QROW+w1]=a2.y; qst[2*QROW+w1]=a2.z; qst[3*QROW+w1]=a2.w;
        qst[4*QROW+w1]=a3.x; qst[5*QROW+w1]=a3.y; qst[6*QROW+w1]=a3.z; qst[7*QROW+w1]=a3.w;
    }
    __syncthreads();

    unsigned long long acc[8][4];
    #pragma unroll
    for (int mi = 0; mi < 8; mi++)
        #pragma unroll
        for (int nj = 0; nj < 4; nj++) acc[mi][nj] = 0ull;

    const int qb = 10*tn;    // swizzled base word of this thread's 8-n group

    for (int c = 0; c < 8; c++){
        const int buf = c & 1;
        float4 p0, p1, p2, p3;
        if (c < 7){
            const int d0 = (c+1)*8;
            p0 = *reinterpret_cast<const float4*>(Qg + (size_t)n0*64 + d0);
            p1 = *reinterpret_cast<const float4*>(Qg + (size_t)n0*64 + d0 + 4);
            p2 = *reinterpret_cast<const float4*>(Qg + (size_t)n1*64 + d0);
            p3 = *reinterpret_cast<const float4*>(Qg + (size_t)n1*64 + d0 + 4);
        }
        const float* qbase = qst + buf*QBUF;
        #pragma unroll
        for (int dd = 0; dd < 8; dd++){
            const int d = c*8 + dd;
            const ulonglong2* kr =
                reinterpret_cast<const ulonglong2*>(kd + d*32 + tm*8);
            ulonglong2 k01 = kr[0], k23 = kr[1], k45 = kr[2], k67 = kr[3];
            const float* qrow = qbase + dd*QROW + qb;
            unsigned long long qpv[4];
            #pragma unroll
            for (int nj = 0; nj < 4; nj++)
                qpv[nj] = *reinterpret_cast<const unsigned long long*>(qrow + 2*nj);
            unsigned long long kp[8] = {k01.x,k01.y,k23.x,k23.y,k45.x,k45.y,k67.x,k67.y};
            #pragma unroll
            for (int mi = 0; mi < 8; mi++){
                #pragma unroll
                for (int nj = 0; nj < 4; nj++)
                    ffma2(acc[mi][nj], kp[mi], qpv[nj]);
            }
        }
        if (c < 7){
            float* dstb = qst + (buf^1)*QBUF;
            dstb[0*QROW+w0]=p0.x; dstb[1*QROW+w0]=p0.y; dstb[2*QROW+w0]=p0.z; dstb[3*QROW+w0]=p0.w;
            dstb[4*QROW+w0]=p1.x; dstb[5*QROW+w0]=p1.y; dstb[6*QROW+w0]=p1.z; dstb[7*QROW+w0]=p1.w;
            dstb[0*QROW+w1]=p2.x; dstb[1*QROW+w1]=p2.y; dstb[2*QROW+w1]=p2.z; dstb[3*QROW+w1]=p2.w;
            dstb[4*QROW+w1]=p3.x; dstb[5*QROW+w1]=p3.y; dstb[6*QROW+w1]=p3.z; dstb[7*QROW+w1]=p3.w;
        }
        __syncthreads();
    }

    // ---- transpose scores into staging (overlays dead Q/K smem) -----------
    // stg[r][mloc], r = (n&7)*128 + (n>>3); n = 8*tn + 2*nj (+1), mloc = tm*8+mi
    #pragma unroll
    for (int mi = 0; mi < 8; mi++){
        #pragma unroll
        for (int nj = 0; nj < 4; nj++){
            float2 p = unpack2(acc[mi][nj]);
            const int r0 = (2*nj+0)*128 + tn;
            const int r1 = (2*nj+1)*128 + tn;
            stg[r0*33 + tm*8 + mi] = p.x;
            stg[r1*33 + tm*8 + mi] = p.y;
        }
    }
    __syncthreads();

    // ---- read own column: col = l (m = m0+l), n-slab = w (64 rows) --------
    float z[64];
    #pragma unroll
    for (int i = 0; i < 64; i++) z[i] = stg[(w*64 + i)*33 + l];

    // ---- Michelot fixed point for sparsemax tau ---------------------------
    float tau = -1.0f;
    for (int iter = 0; iter < 48; iter++){
        float s = 0.f, ccount = 0.f;
        #pragma unroll
        for (int i = 0; i < 64; i++){
            if (z[i] > tau){ s += z[i]; ccount += 1.0f; }
        }
        red_s[w*32 + l] = s; red_c[w*32 + l] = ccount;
        __syncthreads();
        float S = 0.f, Cn = 0.f;
        #pragma unroll
        for (int ww = 0; ww < 16; ww++){ S += red_s[ww*32 + l]; Cn += red_c[ww*32 + l]; }
        const float prev = tau;
        tau = (Cn > 0.f) ? (S - 1.0f)/Cn : tau;
        if (__syncthreads_count(tau != prev) == 0) break;
    }

    // ---- store: out[b][n][h*1024 + m0 + l], n recovered from r ------------
    const int b = bh >> 3, h = bh & 7;
    const size_t obase = (size_t)b*8388608 + (size_t)h*1024 + m0 + l;
    #pragma unroll
    for (int i = 0; i < 64; i++){
        const int r = w*64 + i;
        const int n = ((r & 127) << 3) + (r >> 7);
        float v = z[i] - tau;
        out[obase + (size_t)n*8192] = v > 0.f ? v : 0.f;
    }
}

// ---------------- launcher --------------------------------------------------
extern "C" void kernel_launch(void* const* d_in, const int* in_sizes, int n_in,
                              void* d_out, int out_size){
    const float* x   = (const float*)d_in[0];
    const float* qw  = (const float*)d_in[1];
    const float* kw  = (const float*)d_in[2];
    const float* bnw = (const float*)d_in[3];
    const float* bnb = (const float*)d_in[4];
    float* out = (float*)d_out;
    (void)in_sizes; (void)n_in; (void)out_size;

    cudaFuncSetAttribute(attn_kernel,
                         cudaFuncAttributeMaxDynamicSharedMemorySize, ATTN_SMEM);

    proj_kernel<<<dim3(16, 128), 256>>>(x, qw, kw);
    stats_kernel<<<128, 256>>>();
    norm_kernel<<<16384, 256>>>(bnw, bnb);
    attn_kernel<<<dim3(32, 64), 512, ATTN_SMEM>>>(out);
}